// round 6
// baseline (speedup 1.0000x reference)
#include <cuda_runtime.h>

// out[b,s,d] = x[b,s,d] + enc(s,d)
//   enc(s,d) = sin(s / 10000^(d/D)) if d even else cos(s / 10000^(d/D))
// Shapes: B=8, S=4096, D=1024, fp32. 268 MB traffic (algorithmic floor).
//
// R6: persistent grid-stride variant. R1-R5 proved the kernel sits at the
// mixed 1:1 R/W HBM ceiling (~5.9 TB/s) regardless of occ/MLP/width/cache
// policy. Last untested axis: launch shape. Exactly-resident grid
// (152 SMs x 4 blocks) removes ~6.7 wave transitions and lets loads of
// iteration i+1 overlap stores of iteration i.

#define B_ 8
#define S_ 4096
#define D_ 1024
#define SD4_ ((S_ * D_) / 4)   // 1,048,576 float4 tiles per batch slice
#define NBLK 608               // 152 SMs * 4 resident blocks @ 256 thr

__global__ __launch_bounds__(256) void pe_add_kernel(
    const float4* __restrict__ x, float4* __restrict__ out)
{
    const float c = -(13.287712379549449f / 1024.0f); // -log2(1e4)/D
    const int stride = NBLK * 256;

    for (int idx4 = blockIdx.x * 256 + threadIdx.x; idx4 < SD4_; idx4 += stride) {
        // Front-batch all 8 batch-slice loads (MLP=8 within iteration;
        // independent iterations overlap further).
        float4 v[B_];
#pragma unroll
        for (int b = 0; b < B_; b++)
            v[b] = x[(long long)b * SD4_ + idx4];

        const int d0   = (idx4 & (D_ / 4 - 1)) << 2;
        const float sf = (float)(idx4 >> 8);          // s = idx4 / 256
        const float e0 = sinf(sf * exp2f((float)(d0 + 0) * c)); // even -> sin
        const float e1 = cosf(sf * exp2f((float)(d0 + 1) * c)); // odd  -> cos
        const float e2 = sinf(sf * exp2f((float)(d0 + 2) * c));
        const float e3 = cosf(sf * exp2f((float)(d0 + 3) * c));

#pragma unroll
        for (int b = 0; b < B_; b++) {
            float4 r = v[b];
            r.x += e0; r.y += e1; r.z += e2; r.w += e3;
            __stcs(out + (long long)b * SD4_ + idx4, r);
        }
    }
}

extern "C" void kernel_launch(void* const* d_in, const int* in_sizes, int n_in,
                              void* d_out, int out_size)
{
    const float4* x = (const float4*)d_in[0];
    float4* out = (float4*)d_out;
    pe_add_kernel<<<NBLK, 256>>>(x, out);
}

// round 7
// speedup vs baseline: 1.0805x; 1.0805x over previous
#include <cuda_runtime.h>

// out[b,s,d] = x[b,s,d] + enc(s,d)
//   enc(s,d) = sin(s / 10000^(d/D)) if d even else cos(s / 10000^(d/D))
// Shapes: B=8, S=4096, D=1024, fp32. 268 MB traffic (algorithmic floor).
//
// FINAL (= R5, best measured: 43.49us end-to-end, 5.85-5.97 TB/s).
// Exploration summary (R1-R6): the kernel is pinned at the mixed 1:1 R/W
// HBM3e ceiling (~74% of 8 TB/s spec). Non-binding: occupancy (40% == 82%),
// MLP (4 == 8), access width (128b == 256b), cache hints, launch shape
// (persistent grid-stride REGRESSED 5%: broke read-burst structure).
// Structure: one thread owns one (s, d..d+3) float4 column; computes the 4
// sin/cos encoding values ONCE (hidden under in-flight loads) and applies
// them to all 8 batch slices. Flat launch, loads front-batched (MLP=8),
// evict-first stores.

#define B_ 8
#define S_ 4096
#define D_ 1024
#define SD4_ ((S_ * D_) / 4)   // 1,048,576 float4 tiles per batch slice

__global__ __launch_bounds__(256) void pe_add_kernel(
    const float4* __restrict__ x, float4* __restrict__ out)
{
    const int idx4 = blockIdx.x * blockDim.x + threadIdx.x;   // [0, SD4_)
    const int d0   = (idx4 & (D_ / 4 - 1)) << 2;              // element column in D
    const float sf = (float)(idx4 >> 8);                      // s = idx4 / 256

    // Front-batch all 8 batch-slice loads -> 8 outstanding LDG.128 per thread.
    float4 v[B_];
#pragma unroll
    for (int b = 0; b < B_; b++)
        v[b] = x[(long long)b * SD4_ + idx4];

    // Encoding float4, computed once, hidden under the in-flight loads.
    // angle(d) = s * 10000^(-d/D) = s * exp2(-d * log2(1e4)/D)
    const float c = -(13.287712379549449f / 1024.0f);
    const float e0 = sinf(sf * exp2f((float)(d0 + 0) * c));   // even d -> sin
    const float e1 = cosf(sf * exp2f((float)(d0 + 1) * c));   // odd d  -> cos
    const float e2 = sinf(sf * exp2f((float)(d0 + 2) * c));
    const float e3 = cosf(sf * exp2f((float)(d0 + 3) * c));

#pragma unroll
    for (int b = 0; b < B_; b++) {
        float4 r = v[b];
        r.x += e0; r.y += e1; r.z += e2; r.w += e3;
        __stcs(out + (long long)b * SD4_ + idx4, r);
    }
}

extern "C" void kernel_launch(void* const* d_in, const int* in_sizes, int n_in,
                              void* d_out, int out_size)
{
    const float4* x = (const float4*)d_in[0];
    float4* out = (float4*)d_out;
    pe_add_kernel<<<SD4_ / 256, 256>>>(x, out);
}

// round 8
// speedup vs baseline: 1.1163x; 1.0331x over previous
#include <cuda_runtime.h>

// out[b,s,d] = x[b,s,d] + enc(s,d)
//   enc(s,d) = sin(s / 10000^(d/D)) if d even else cos(s / 10000^(d/D))
// Shapes: B=8, S=4096, D=1024, fp32. 268 MB traffic (algorithmic floor).
//
// R8 = FINAL R5 structure with the last untested dial: 512-thread blocks
// (wider contiguous read span per block for DRAM row locality; all else
// identical). R1-R7 established the mixed 1:1 R/W HBM ceiling (~74% of
// 8 TB/s) as the binder; occ/MLP/width/cache-policy/launch-shape all
// non-binding; harness noise floor measured at +/-1.5us.
//
// Structure: one thread owns one (s, d..d+3) float4 column; computes the 4
// sin/cos encoding values ONCE (hidden under in-flight loads) and applies
// them to all 8 batch slices. Flat launch, loads front-batched (MLP=8),
// evict-first stores.

#define B_ 8
#define S_ 4096
#define D_ 1024
#define SD4_ ((S_ * D_) / 4)   // 1,048,576 float4 tiles per batch slice
#define TPB 512

__global__ __launch_bounds__(TPB) void pe_add_kernel(
    const float4* __restrict__ x, float4* __restrict__ out)
{
    const int idx4 = blockIdx.x * TPB + threadIdx.x;          // [0, SD4_)
    const int d0   = (idx4 & (D_ / 4 - 1)) << 2;              // element column in D
    const float sf = (float)(idx4 >> 8);                      // s = idx4 / 256

    // Front-batch all 8 batch-slice loads -> 8 outstanding LDG.128 per thread.
    float4 v[B_];
#pragma unroll
    for (int b = 0; b < B_; b++)
        v[b] = x[(long long)b * SD4_ + idx4];

    // Encoding float4, computed once, hidden under the in-flight loads.
    // angle(d) = s * 10000^(-d/D) = s * exp2(-d * log2(1e4)/D)
    const float c = -(13.287712379549449f / 1024.0f);
    const float e0 = sinf(sf * exp2f((float)(d0 + 0) * c));   // even d -> sin
    const float e1 = cosf(sf * exp2f((float)(d0 + 1) * c));   // odd d  -> cos
    const float e2 = sinf(sf * exp2f((float)(d0 + 2) * c));
    const float e3 = cosf(sf * exp2f((float)(d0 + 3) * c));

#pragma unroll
    for (int b = 0; b < B_; b++) {
        float4 r = v[b];
        r.x += e0; r.y += e1; r.z += e2; r.w += e3;
        __stcs(out + (long long)b * SD4_ + idx4, r);
    }
}

extern "C" void kernel_launch(void* const* d_in, const int* in_sizes, int n_in,
                              void* d_out, int out_size)
{
    const float4* x = (const float4*)d_in[0];
    float4* out = (float4*)d_out;
    pe_add_kernel<<<SD4_ / TPB, TPB>>>(x, out);
}